// round 10
// baseline (speedup 1.0000x reference)
#include <cuda_runtime.h>

// Problem: B=1, L=768, D_SINGLE=384, D_PAIR=128
//   left  = s @ W[:384] + bias   (768x128)
//   right = s @ W[384:]          (768x128)
//   out[i,j,f] = left[i,f] + right[j,f]      -> 768*768*128 fp32 = 302 MB
//
// R10: single fused kernel, distributed readiness flags.
//   Blocks 0..127: compute proj tile (6 rows of left+right), publish flag[bid].
//   All 4608 blocks: wait ONLY on the flags their bcast tile needs
//   (1 left-tile flag + ~22 right-chunk flags), then stream the tile out.
//   Flags live on separate 128B lines; one polling thread per block.
//
// Inputs (metadata order): s (768*384 f32), z (UNUSED), W (768*128 f32), bias (128 f32)

#define L_DIM 768
#define DS 384
#define DP 128
#define TI 6                       // rows per proj block -> 128 proj blocks
#define NPROJ (L_DIM / TI)         // 128
#define NCHUNK (L_DIM / 128)       // 6
#define GRID (L_DIM * NCHUNK)      // 4608

// scratch (no cudaMalloc allowed)
__device__ float g_left[L_DIM * DP];          // includes bias
__device__ float g_right[L_DIM * DP];
__device__ unsigned g_flag[NPROJ * 32];       // flag b at g_flag[b*32] (128B spacing)
__device__ unsigned g_exit;                   // for end-of-launch flag reset

__device__ __forceinline__ void flag_set(int b) {
    asm volatile("st.release.gpu.global.u32 [%0], 1;"
                 :: "l"(&g_flag[b * 32]) : "memory");
}
__device__ __forceinline__ unsigned flag_get(int b) {
    unsigned v;
    asm volatile("ld.acquire.gpu.global.u32 %0, [%1];"
                 : "=r"(v) : "l"(&g_flag[b * 32]));
    return v;
}

__global__ __launch_bounds__(256) void fused_kernel(
    const float* __restrict__ s,     // [768, 384]
    const float* __restrict__ W,     // [768, 128]
    const float* __restrict__ bias,  // [128]
    float* __restrict__ out)         // [768, 768, 128]
{
    __shared__ float s_sh[TI][DS];
    const int bid = blockIdx.x;
    const int tid = threadIdx.x;

    // ---------------- producer phase: blocks 0..127 ----------------
    if (bid < NPROJ) {
        const int i0 = bid * TI;
        for (int idx = tid; idx < TI * DS; idx += 256) {
            int r = idx / DS, c = idx % DS;
            s_sh[r][c] = s[(size_t)(i0 + r) * DS + c];
        }
        __syncthreads();

        const int f    = tid & 127;
        const int half = tid >> 7;                  // 0 = left, 1 = right
        const float* Wcol = W + (size_t)(half ? DS : 0) * DP + f;

        float acc[TI];
#pragma unroll
        for (int ii = 0; ii < TI; ii++) acc[ii] = 0.f;

        const float4 (*s4)[DS / 4] = reinterpret_cast<const float4 (*)[DS / 4]>(s_sh);

#pragma unroll 4
        for (int k4 = 0; k4 < DS / 4; k4++) {
            const int kb = k4 * 4;
            float w0 = Wcol[(size_t)(kb + 0) * DP];
            float w1 = Wcol[(size_t)(kb + 1) * DP];
            float w2 = Wcol[(size_t)(kb + 2) * DP];
            float w3 = Wcol[(size_t)(kb + 3) * DP];
#pragma unroll
            for (int ii = 0; ii < TI; ii++) {
                float4 sv = s4[ii][k4];             // one LDS.128, warp-broadcast
                acc[ii] = fmaf(sv.x, w0, acc[ii]);
                acc[ii] = fmaf(sv.y, w1, acc[ii]);
                acc[ii] = fmaf(sv.z, w2, acc[ii]);
                acc[ii] = fmaf(sv.w, w3, acc[ii]);
            }
        }

        if (half == 0) {
            const float b = bias[f];
#pragma unroll
            for (int ii = 0; ii < TI; ii++)
                g_left[(size_t)(i0 + ii) * DP + f] = acc[ii] + b;
        } else {
#pragma unroll
            for (int ii = 0; ii < TI; ii++)
                g_right[(size_t)(i0 + ii) * DP + f] = acc[ii];
        }

        __syncthreads();
        if (tid == 0) {
            __threadfence();         // stores gpu-visible before the flag
            flag_set(bid);
        }
    }

    // ---------------- tile assignment ----------------
    const int i  = bid / NCHUNK;            // 0..767  (low bid -> low flags needed)
    const int j0 = (bid % NCHUNK) * 128;

    // ---------------- fine-grained wait ----------------
    if (tid == 0) {
        const int fi  = i / TI;                   // left-tile producer
        const int fb0 = j0 / TI;                  // right-chunk producers
        const int fb1 = (j0 + 127) / TI;
        // poll each needed flag; spread across distinct 128B lines
        for (int b = fb0; b <= fb1; b++)
            while (!flag_get(b)) __nanosleep(128);
        while (!flag_get(fi)) __nanosleep(128);
    }
    __syncthreads();                              // broadcast acquires to block

    // ---------------- consumer phase ----------------
    {
        const int f4 = tid & 31;
        const int jl = tid >> 5;

        const float4* left4  = reinterpret_cast<const float4*>(g_left);
        const float4* right4 = reinterpret_cast<const float4*>(g_right);
        float4* out4 = reinterpret_cast<float4*>(out);

        const float4 lv = left4[(size_t)i * 32 + f4];   // includes bias
        const size_t orow = ((size_t)i * L_DIM + j0) * 32 + f4;

#pragma unroll 4
        for (int jj = jl; jj < 128; jj += 8) {
            float4 rv = __ldg(right4 + (size_t)(j0 + jj) * 32 + f4);
            float4 o;
            o.x = lv.x + rv.x;
            o.y = lv.y + rv.y;
            o.z = lv.z + rv.z;
            o.w = lv.w + rv.w;
            __stcs(out4 + orow + (size_t)jj * 32, o);   // evict-first stream
        }
    }

    // ---------------- epilogue: last block resets flags ----------------
    __syncthreads();
    if (tid == 0) {
        __threadfence();
        unsigned e = atomicAdd(&g_exit, 1u);
        if (e == GRID - 1) {                    // every other block is done
            for (int b = 0; b < NPROJ; b++) g_flag[b * 32] = 0u;
            __threadfence();
            atomicExch(&g_exit, 0u);
        }
    }
}

// ---------------------------------------------------------------------------
extern "C" void kernel_launch(void* const* d_in, const int* in_sizes, int n_in,
                              void* d_out, int out_size)
{
    const float* s    = (const float*)d_in[0];
    // d_in[1] = z : intentionally unused (reference never reads it)
    const float* W    = (const float*)d_in[2];
    const float* bias = (const float*)d_in[3];
    float* out = (float*)d_out;

    fused_kernel<<<GRID, 256>>>(s, W, bias, out);
}

// round 11
// speedup vs baseline: 1.2440x; 1.2440x over previous
#include <cuda_runtime.h>

// Problem: B=1, L=768, D_SINGLE=384, D_PAIR=128
//   left  = s @ W[:384] + bias   (768x128)   [bias folded into left]
//   right = s @ W[384:]          (768x128)
//   out[i,j,f] = left[i,f] + right[j,f]      -> 768*768*128 fp32 = 302 MB
//
// R11 = R5 (best, 65.95us) with TI_B=2 bcast tiling:
//   each block handles 2 i-rows x one 128-j chunk -> one right[j] read feeds
//   2 output rows (L2/L1 read wavefronts halved) while grid stays 2304
//   (occupancy preserved — R9 showed grid 576 starves the store streams).
// Store policy: pure __stcs evict-first (R6/R8: any retention costs +20us).
// Proj + PDL chaining identical to R5.
//
// Inputs (metadata order): s (768*384 f32), z (UNUSED), W (768*128 f32), bias (128 f32)

#define L_DIM 768
#define DS 384
#define DP 128
#define TI 6          // rows per proj block -> 128 blocks (single wave)
#define TI_B 2        // i-rows per bcast block -> grid (6, 384) = 2304

// scratch (no cudaMalloc allowed)
__device__ float g_left[L_DIM * DP];    // includes bias
__device__ float g_right[L_DIM * DP];

// ---------------------------------------------------------------------------
// Kernel 1: projections. 128 blocks x 256 threads. (R5 best, unchanged)
// ---------------------------------------------------------------------------
__global__ __launch_bounds__(256) void proj_kernel(
    const float* __restrict__ s,     // [768, 384]
    const float* __restrict__ W,     // [768, 128]
    const float* __restrict__ bias)  // [128]
{
    __shared__ float s_sh[TI][DS];
    const int i0  = blockIdx.x * TI;
    const int tid = threadIdx.x;

    for (int idx = tid; idx < TI * DS; idx += 256) {
        int r = idx / DS, c = idx % DS;
        s_sh[r][c] = s[(size_t)(i0 + r) * DS + c];
    }
    __syncthreads();

    const int f    = tid & 127;
    const int half = tid >> 7;                    // 0 = left, 1 = right
    const float* Wcol = W + (size_t)(half ? DS : 0) * DP + f;

    float acc[TI];
#pragma unroll
    for (int ii = 0; ii < TI; ii++) acc[ii] = 0.f;

    const float4 (*s4)[DS / 4] = reinterpret_cast<const float4 (*)[DS / 4]>(s_sh);

#pragma unroll 4
    for (int k4 = 0; k4 < DS / 4; k4++) {
        const int kb = k4 * 4;
        float w0 = Wcol[(size_t)(kb + 0) * DP];
        float w1 = Wcol[(size_t)(kb + 1) * DP];
        float w2 = Wcol[(size_t)(kb + 2) * DP];
        float w3 = Wcol[(size_t)(kb + 3) * DP];
#pragma unroll
        for (int ii = 0; ii < TI; ii++) {
            float4 sv = s4[ii][k4];               // one LDS.128, warp-broadcast
            acc[ii] = fmaf(sv.x, w0, acc[ii]);
            acc[ii] = fmaf(sv.y, w1, acc[ii]);
            acc[ii] = fmaf(sv.z, w2, acc[ii]);
            acc[ii] = fmaf(sv.w, w3, acc[ii]);
        }
    }

    if (half == 0) {
        const float b = bias[f];
#pragma unroll
        for (int ii = 0; ii < TI; ii++)
            g_left[(size_t)(i0 + ii) * DP + f] = acc[ii] + b;
    } else {
#pragma unroll
        for (int ii = 0; ii < TI; ii++)
            g_right[(size_t)(i0 + ii) * DP + f] = acc[ii];
    }

    __syncthreads();
    __threadfence();
    cudaTriggerProgrammaticLaunchCompletion();
}

// ---------------------------------------------------------------------------
// Kernel 2: broadcast-add, 2 i-rows per block.
// grid = (6 j-chunks, 384 i-pairs). 256 threads: f4 = tid&31, jl = tid>>5.
// One right[j] float4 read -> 2 output stores.
// ---------------------------------------------------------------------------
__global__ __launch_bounds__(256) void bcast_kernel(float* __restrict__ out)
{
    const int i0  = blockIdx.y * TI_B;
    const int j0  = blockIdx.x * 128;
    const int tid = threadIdx.x;
    const int f4  = tid & 31;
    const int jl  = tid >> 5;

    cudaGridDependencySynchronize();   // PDL: wait for proj's triggered stores

    const float4* left4  = reinterpret_cast<const float4*>(g_left);
    const float4* right4 = reinterpret_cast<const float4*>(g_right);
    float4* out4 = reinterpret_cast<float4*>(out);

    const float4 lv0 = left4[(size_t)(i0 + 0) * 32 + f4];   // includes bias
    const float4 lv1 = left4[(size_t)(i0 + 1) * 32 + f4];

    const size_t orow0 = ((size_t)(i0 + 0) * L_DIM + j0) * 32 + f4;
    const size_t orow1 = ((size_t)(i0 + 1) * L_DIM + j0) * 32 + f4;

#pragma unroll 4
    for (int jj = jl; jj < 128; jj += 8) {
        float4 rv = __ldg(right4 + (size_t)(j0 + jj) * 32 + f4);
        float4 o0, o1;
        o0.x = lv0.x + rv.x;  o0.y = lv0.y + rv.y;
        o0.z = lv0.z + rv.z;  o0.w = lv0.w + rv.w;
        o1.x = lv1.x + rv.x;  o1.y = lv1.y + rv.y;
        o1.z = lv1.z + rv.z;  o1.w = lv1.w + rv.w;
        __stcs(out4 + orow0 + (size_t)jj * 32, o0);   // evict-first stream
        __stcs(out4 + orow1 + (size_t)jj * 32, o1);
    }
}

// ---------------------------------------------------------------------------
extern "C" void kernel_launch(void* const* d_in, const int* in_sizes, int n_in,
                              void* d_out, int out_size)
{
    const float* s    = (const float*)d_in[0];
    // d_in[1] = z : intentionally unused (reference never reads it)
    const float* W    = (const float*)d_in[2];
    const float* bias = (const float*)d_in[3];
    float* out = (float*)d_out;

    proj_kernel<<<L_DIM / TI, 256>>>(s, W, bias);

    cudaLaunchConfig_t cfg = {};
    cfg.gridDim  = dim3(L_DIM / 128, L_DIM / TI_B);   // (6, 384)
    cfg.blockDim = dim3(256, 1, 1);
    cfg.dynamicSmemBytes = 0;
    cfg.stream = 0;

    cudaLaunchAttribute attr;
    attr.id = cudaLaunchAttributeProgrammaticStreamSerialization;
    attr.val.programmaticStreamSerializationAllowed = 1;
    cfg.attrs = &attr;
    cfg.numAttrs = 1;

    cudaLaunchKernelEx(&cfg, bcast_kernel, out);
}

// round 12
// speedup vs baseline: 1.2511x; 1.0057x over previous
#include <cuda_runtime.h>

// Problem: B=1, L=768, D_SINGLE=384, D_PAIR=128
//   left  = s @ W[:384] + bias   (768x128)   [bias folded into left]
//   right = s @ W[384:]          (768x128)
//   out[i,j,f] = left[i,f] + right[j,f]      -> 768*768*128 fp32 = 302 MB
//
// R12 = R5 (champion bcast, untouched) + f32x2 packed-FMA proj:
//   fma.rn.f32x2 does 2 fp32 FMAs per instruction (sm_103a, PTX-only).
//   k packed pairwise -> FFMA issue slots halved (2304 -> 1152 per thread).
//
// Inputs (metadata order): s (768*384 f32), z (UNUSED), W (768*128 f32), bias (128 f32)

#define L_DIM 768
#define DS 384
#define DP 128
#define TI 6          // rows per proj block -> 128 blocks (single wave)

// scratch (no cudaMalloc allowed)
__device__ float g_left[L_DIM * DP];    // includes bias
__device__ float g_right[L_DIM * DP];

// ---------------------------------------------------------------------------
// packed fp32x2 FMA: d = a*b + c elementwise on 2 floats (one instruction)
// ---------------------------------------------------------------------------
__device__ __forceinline__ float2 ffma2(float2 a, float2 b, float2 c) {
    unsigned long long ra = *reinterpret_cast<unsigned long long*>(&a);
    unsigned long long rb = *reinterpret_cast<unsigned long long*>(&b);
    unsigned long long rc = *reinterpret_cast<unsigned long long*>(&c);
    unsigned long long rd;
    asm("fma.rn.f32x2 %0, %1, %2, %3;" : "=l"(rd) : "l"(ra), "l"(rb), "l"(rc));
    return *reinterpret_cast<float2*>(&rd);
}

// ---------------------------------------------------------------------------
// Kernel 1: projections. 128 blocks x 256 threads.
// f = tid&127 output column, half = tid>>7 selects left/right.
// s staged in smem, consumed as float4; k packed pairwise into f32x2 FMAs.
// ---------------------------------------------------------------------------
__global__ __launch_bounds__(256) void proj_kernel(
    const float* __restrict__ s,     // [768, 384]
    const float* __restrict__ W,     // [768, 128]
    const float* __restrict__ bias)  // [128]
{
    __shared__ float s_sh[TI][DS];
    const int i0  = blockIdx.x * TI;
    const int tid = threadIdx.x;

    for (int idx = tid; idx < TI * DS; idx += 256) {
        int r = idx / DS, c = idx % DS;
        s_sh[r][c] = s[(size_t)(i0 + r) * DS + c];
    }
    __syncthreads();

    const int f    = tid & 127;
    const int half = tid >> 7;                    // 0 = left, 1 = right
    const float* Wcol = W + (size_t)(half ? DS : 0) * DP + f;

    // two f32x2 accumulators per row (even/odd k pairs)
    float2 accA[TI], accB[TI];
#pragma unroll
    for (int ii = 0; ii < TI; ii++) {
        accA[ii] = make_float2(0.f, 0.f);
        accB[ii] = make_float2(0.f, 0.f);
    }

    const float4 (*s4)[DS / 4] = reinterpret_cast<const float4 (*)[DS / 4]>(s_sh);

#pragma unroll 4
    for (int k4 = 0; k4 < DS / 4; k4++) {
        const int kb = k4 * 4;
        float2 w01 = make_float2(Wcol[(size_t)(kb + 0) * DP],
                                 Wcol[(size_t)(kb + 1) * DP]);
        float2 w23 = make_float2(Wcol[(size_t)(kb + 2) * DP],
                                 Wcol[(size_t)(kb + 3) * DP]);
#pragma unroll
        for (int ii = 0; ii < TI; ii++) {
            float4 sv = s4[ii][k4];               // one LDS.128, warp-broadcast
            accA[ii] = ffma2(make_float2(sv.x, sv.y), w01, accA[ii]);
            accB[ii] = ffma2(make_float2(sv.z, sv.w), w23, accB[ii]);
        }
    }

    if (half == 0) {
        const float b = bias[f];
#pragma unroll
        for (int ii = 0; ii < TI; ii++)
            g_left[(size_t)(i0 + ii) * DP + f] =
                (accA[ii].x + accA[ii].y) + (accB[ii].x + accB[ii].y) + b;
    } else {
#pragma unroll
        for (int ii = 0; ii < TI; ii++)
            g_right[(size_t)(i0 + ii) * DP + f] =
                (accA[ii].x + accA[ii].y) + (accB[ii].x + accB[ii].y);
    }

    __syncthreads();
    __threadfence();
    cudaTriggerProgrammaticLaunchCompletion();
}

// ---------------------------------------------------------------------------
// Kernel 2: broadcast-add. EXACTLY the R5 champion (do not touch).
// grid = (6 j-chunks, 768 i). 256 threads: f4 = tid&31, jl = tid>>5.
// ---------------------------------------------------------------------------
__global__ __launch_bounds__(256) void bcast_kernel(float* __restrict__ out)
{
    const int i   = blockIdx.y;
    const int j0  = blockIdx.x * 128;
    const int tid = threadIdx.x;
    const int f4  = tid & 31;
    const int jl  = tid >> 5;

    cudaGridDependencySynchronize();   // PDL: wait for proj's triggered stores

    const float4* left4  = reinterpret_cast<const float4*>(g_left);
    const float4* right4 = reinterpret_cast<const float4*>(g_right);
    float4* out4 = reinterpret_cast<float4*>(out);

    const float4 lv = left4[(size_t)i * 32 + f4];       // includes bias
    const size_t orow = ((size_t)i * L_DIM + j0) * 32 + f4;

#pragma unroll 4
    for (int jj = jl; jj < 128; jj += 8) {
        float4 rv = __ldg(right4 + (size_t)(j0 + jj) * 32 + f4);
        float4 o;
        o.x = lv.x + rv.x;
        o.y = lv.y + rv.y;
        o.z = lv.z + rv.z;
        o.w = lv.w + rv.w;
        __stcs(out4 + orow + (size_t)jj * 32, o);       // evict-first stream
    }
}

// ---------------------------------------------------------------------------
extern "C" void kernel_launch(void* const* d_in, const int* in_sizes, int n_in,
                              void* d_out, int out_size)
{
    const float* s    = (const float*)d_in[0];
    // d_in[1] = z : intentionally unused (reference never reads it)
    const float* W    = (const float*)d_in[2];
    const float* bias = (const float*)d_in[3];
    float* out = (float*)d_out;

    proj_kernel<<<L_DIM / TI, 256>>>(s, W, bias);

    cudaLaunchConfig_t cfg = {};
    cfg.gridDim  = dim3(L_DIM / 128, L_DIM);   // (6, 768)
    cfg.blockDim = dim3(256, 1, 1);
    cfg.dynamicSmemBytes = 0;
    cfg.stream = 0;

    cudaLaunchAttribute attr;
    attr.id = cudaLaunchAttributeProgrammaticStreamSerialization;
    attr.val.programmaticStreamSerializationAllowed = 1;
    cfg.attrs = &attr;
    cfg.numAttrs = 1;

    cudaLaunchKernelEx(&cfg, bcast_kernel, out);
}

// round 13
// speedup vs baseline: 1.2770x; 1.0208x over previous
#include <cuda_runtime.h>

// Problem: B=1, L=768, D_SINGLE=384, D_PAIR=128
//   left  = s @ W[:384] + bias   (768x128)   [bias folded into left]
//   right = s @ W[384:]          (768x128)
//   out[i,j,f] = left[i,f] + right[j,f]      -> 768*768*128 fp32 = 302 MB
//
// FINAL (= R5 champion, 65.95us). Period is pinned by the 302 MB DRAM write
// stream (~57us at effective write BW) + ~9us proj/boundary. Discriminated:
//  - evict-first (__stcs) stores mandatory: any L2-retention policy +20us
//  - bcast geometry optimal: 1 i-row/block, 8 warps = 8 consecutive j-rows
//    per step (contiguous 4KB write front), grid 4608 for occupancy
//  - software-sync fusion loses (+2.5..+19us); PDL chaining is free
//  - proj compute tweaks invisible (hidden under previous replay's drain)
//
// Inputs (metadata order): s (768*384 f32), z (UNUSED), W (768*128 f32), bias (128 f32)

#define L_DIM 768
#define DS 384
#define DP 128
#define TI 6          // rows per proj block -> 128 blocks (single wave)

// scratch (no cudaMalloc allowed)
__device__ float g_left[L_DIM * DP];    // includes bias
__device__ float g_right[L_DIM * DP];

// ---------------------------------------------------------------------------
// Kernel 1: projections. 128 blocks x 256 threads.
// f = tid&127 output column, half = tid>>7 selects left/right.
// s staged in smem, consumed as float4 (warp-broadcast LDS.128).
// W scalar LDG, coalesced across the 128 f-threads (L2-hot).
// ---------------------------------------------------------------------------
__global__ __launch_bounds__(256) void proj_kernel(
    const float* __restrict__ s,     // [768, 384]
    const float* __restrict__ W,     // [768, 128]
    const float* __restrict__ bias)  // [128]
{
    __shared__ float s_sh[TI][DS];
    const int i0  = blockIdx.x * TI;
    const int tid = threadIdx.x;

    for (int idx = tid; idx < TI * DS; idx += 256) {
        int r = idx / DS, c = idx % DS;
        s_sh[r][c] = s[(size_t)(i0 + r) * DS + c];
    }
    __syncthreads();

    const int f    = tid & 127;
    const int half = tid >> 7;                    // 0 = left, 1 = right
    const float* Wcol = W + (size_t)(half ? DS : 0) * DP + f;

    float acc[TI];
#pragma unroll
    for (int ii = 0; ii < TI; ii++) acc[ii] = 0.f;

    const float4 (*s4)[DS / 4] = reinterpret_cast<const float4 (*)[DS / 4]>(s_sh);

#pragma unroll 4
    for (int k4 = 0; k4 < DS / 4; k4++) {
        const int kb = k4 * 4;
        float w0 = Wcol[(size_t)(kb + 0) * DP];
        float w1 = Wcol[(size_t)(kb + 1) * DP];
        float w2 = Wcol[(size_t)(kb + 2) * DP];
        float w3 = Wcol[(size_t)(kb + 3) * DP];
#pragma unroll
        for (int ii = 0; ii < TI; ii++) {
            float4 sv = s4[ii][k4];               // one LDS.128, warp-broadcast
            acc[ii] = fmaf(sv.x, w0, acc[ii]);
            acc[ii] = fmaf(sv.y, w1, acc[ii]);
            acc[ii] = fmaf(sv.z, w2, acc[ii]);
            acc[ii] = fmaf(sv.w, w3, acc[ii]);
        }
    }

    if (half == 0) {
        const float b = bias[f];
#pragma unroll
        for (int ii = 0; ii < TI; ii++)
            g_left[(size_t)(i0 + ii) * DP + f] = acc[ii] + b;
    } else {
#pragma unroll
        for (int ii = 0; ii < TI; ii++)
            g_right[(size_t)(i0 + ii) * DP + f] = acc[ii];
    }

    __syncthreads();
    __threadfence();
    cudaTriggerProgrammaticLaunchCompletion();
}

// ---------------------------------------------------------------------------
// Kernel 2: broadcast-add. out[i,j,f] = left[i,f] + right[j,f].
// grid = (6 j-chunks, 768 i). 256 threads: f4 = tid&31, jl = tid>>5.
// Per jj-step the 8 warps write 8 consecutive j rows = contiguous 4KB.
// Evict-first streaming stores; right[] stays L2-resident.
// ---------------------------------------------------------------------------
__global__ __launch_bounds__(256) void bcast_kernel(float* __restrict__ out)
{
    const int i   = blockIdx.y;
    const int j0  = blockIdx.x * 128;
    const int tid = threadIdx.x;
    const int f4  = tid & 31;
    const int jl  = tid >> 5;

    cudaGridDependencySynchronize();   // PDL: wait for proj's triggered stores

    const float4* left4  = reinterpret_cast<const float4*>(g_left);
    const float4* right4 = reinterpret_cast<const float4*>(g_right);
    float4* out4 = reinterpret_cast<float4*>(out);

    const float4 lv = left4[(size_t)i * 32 + f4];       // includes bias
    const size_t orow = ((size_t)i * L_DIM + j0) * 32 + f4;

#pragma unroll 4
    for (int jj = jl; jj < 128; jj += 8) {
        float4 rv = __ldg(right4 + (size_t)(j0 + jj) * 32 + f4);
        float4 o;
        o.x = lv.x + rv.x;
        o.y = lv.y + rv.y;
        o.z = lv.z + rv.z;
        o.w = lv.w + rv.w;
        __stcs(out4 + orow + (size_t)jj * 32, o);       // evict-first stream
    }
}

// ---------------------------------------------------------------------------
extern "C" void kernel_launch(void* const* d_in, const int* in_sizes, int n_in,
                              void* d_out, int out_size)
{
    const float* s    = (const float*)d_in[0];
    // d_in[1] = z : intentionally unused (reference never reads it)
    const float* W    = (const float*)d_in[2];
    const float* bias = (const float*)d_in[3];
    float* out = (float*)d_out;

    proj_kernel<<<L_DIM / TI, 256>>>(s, W, bias);

    cudaLaunchConfig_t cfg = {};
    cfg.gridDim  = dim3(L_DIM / 128, L_DIM);   // (6, 768)
    cfg.blockDim = dim3(256, 1, 1);
    cfg.dynamicSmemBytes = 0;
    cfg.stream = 0;

    cudaLaunchAttribute attr;
    attr.id = cudaLaunchAttributeProgrammaticStreamSerialization;
    attr.val.programmaticStreamSerializationAllowed = 1;
    cfg.attrs = &attr;
    cfg.numAttrs = 1;

    cudaLaunchKernelEx(&cfg, bcast_kernel, out);
}